// round 8
// baseline (speedup 1.0000x reference)
#include <cuda_runtime.h>
#include <cuda_fp16.h>

#define NN 50000
#define NE 1600000
#define CH 64
#define INF 32
#define CAP 128           // per-node bucket capacity (mean deg = 32; P(>128) ~ e^-60)

// ---- device scratch (both graphs batched; no allocation allowed) ----
__device__ __align__(16)  int     g_cnt[2 * NN];
__device__ __align__(16)  int     g_src[2 * NN * CAP];
__device__ __align__(128) float   g_A[2 * NN * CH];          // per-node self term, fp32
__device__ __align__(128) __half2 g_B[2 * NN * (CH / 2)];    // gathered term, fp16 (12.8MB -> L2)
__device__ __align__(128) float   g_h[2 * NN * CH];          // layer-1 output
__device__ __align__(16)  float   g_Wd1[INF * CH];           // W1_top - W1_bot
__device__ __align__(16)  float   g_Wd2[CH * CH];            // W2_top - W2_bot

// ---------- fused init: zero counters + weight diffs ----------
__global__ void k_init(const float* __restrict__ W1, const float* __restrict__ W2) {
    int i = blockIdx.x * blockDim.x + threadIdx.x;
    if (i < 2 * NN) g_cnt[i] = 0;
    if (i < INF * CH) g_Wd1[i] = W1[i] - W1[INF * CH + i];
    if (i < CH * CH)  g_Wd2[i] = W2[i] - W2[CH * CH + i];
}

// ---------- bucket build: 8 independent edge chains per thread (MLP=8) ----------
// edge_index is int32 on device (JAX x64 disabled). Both graphs in one launch.
__global__ void k_scatter(const int* __restrict__ ei1, const int* __restrict__ ei2) {
    int t = blockIdx.x * blockDim.x + threadIdx.x;
    const int QH = NE / 8;                 // 8-edge groups per graph
    if (t >= 2 * QH) return;
    int g = t >= QH;
    int i = t - g * QH;
    const int* ei = g ? ei2 : ei1;
    int4 sa = ((const int4*)ei)[2 * i];
    int4 sb = ((const int4*)ei)[2 * i + 1];
    int4 da = ((const int4*)(ei + NE))[2 * i];
    int4 db = ((const int4*)(ei + NE))[2 * i + 1];
    int nb = g * NN;
    int n0 = nb + da.x, n1 = nb + da.y, n2 = nb + da.z, n3 = nb + da.w;
    int n4 = nb + db.x, n5 = nb + db.y, n6 = nb + db.z, n7 = nb + db.w;
    int p0 = atomicAdd(&g_cnt[n0], 1);
    int p1 = atomicAdd(&g_cnt[n1], 1);
    int p2 = atomicAdd(&g_cnt[n2], 1);
    int p3 = atomicAdd(&g_cnt[n3], 1);
    int p4 = atomicAdd(&g_cnt[n4], 1);
    int p5 = atomicAdd(&g_cnt[n5], 1);
    int p6 = atomicAdd(&g_cnt[n6], 1);
    int p7 = atomicAdd(&g_cnt[n7], 1);
    if (p0 < CAP) g_src[n0 * CAP + p0] = sa.x;
    if (p1 < CAP) g_src[n1 * CAP + p1] = sa.y;
    if (p2 < CAP) g_src[n2 * CAP + p2] = sa.z;
    if (p3 < CAP) g_src[n3 * CAP + p3] = sa.w;
    if (p4 < CAP) g_src[n4 * CAP + p4] = sb.x;
    if (p5 < CAP) g_src[n5 * CAP + p5] = sb.y;
    if (p6 < CAP) g_src[n6 * CAP + p6] = sb.z;
    if (p7 < CAP) g_src[n7 * CAP + p7] = sb.w;
}

// ---------- mlp1: register-blocked GEMM. block = 128 nodes, thread = 4 nodes x 8 ch ----------
#define XS1 132   // padded row stride for sX (breaks bank-conflict on staging stores)
__global__ void __launch_bounds__(256) k_mlp1(const float* __restrict__ x1,
                                              const float* __restrict__ x2,
                                              const float* __restrict__ b1,
                                              const float* __restrict__ W1) {
    __shared__ float sWd[INF * CH];        // 8KB
    __shared__ float sWb[INF * CH];        // 8KB
    __shared__ float sX[INF * XS1];        // ~16.5KB, k-major with pad
    int tid = threadIdx.x;
    int base = blockIdx.x * 128;

    {
        float4* d4 = (float4*)sWd; float4* b4 = (float4*)sWb;
        const float4* gd = (const float4*)g_Wd1;
        const float4* gb = (const float4*)(W1 + INF * CH);
        d4[tid] = gd[tid];           d4[tid + 256] = gd[tid + 256];
        b4[tid] = gb[tid];           b4[tid + 256] = gb[tid + 256];
    }
    #pragma unroll
    for (int i = 0; i < 4; i++) {
        int idx = tid + i * 256;             // 0..1023
        int nl = idx >> 3;                   // local node 0..127
        int j  = idx & 7;                    // float4 index within 32-float row
        int n = base + nl;
        if (n < 2 * NN) {
            const float* xr = (n < NN) ? (x1 + (size_t)n * INF)
                                       : (x2 + (size_t)(n - NN) * INF);
            float4 v = *(const float4*)(xr + 4 * j);
            sX[(4 * j + 0) * XS1 + nl] = v.x;
            sX[(4 * j + 1) * XS1 + nl] = v.y;
            sX[(4 * j + 2) * XS1 + nl] = v.z;
            sX[(4 * j + 3) * XS1 + nl] = v.w;
        }
    }
    __syncthreads();

    int nq = tid & 31;        // node quad
    int co = tid >> 5;        // channel oct (uniform per warp)
    float a[4][8], b[4][8];
    #pragma unroll
    for (int j = 0; j < 8; j++) {
        float bv = __ldg(b1 + co * 8 + j);
        #pragma unroll
        for (int i = 0; i < 4; i++) { a[i][j] = bv; b[i][j] = 0.f; }
    }

    #pragma unroll
    for (int k = 0; k < INF; k++) {
        float4 xv = *(const float4*)(sX + k * XS1 + nq * 4);
        float4 wd0 = *(const float4*)(sWd + k * CH + co * 8);
        float4 wd1 = *(const float4*)(sWd + k * CH + co * 8 + 4);
        float4 wb0 = *(const float4*)(sWb + k * CH + co * 8);
        float4 wb1 = *(const float4*)(sWb + k * CH + co * 8 + 4);
        float xs[4] = {xv.x, xv.y, xv.z, xv.w};
        float wds[8] = {wd0.x, wd0.y, wd0.z, wd0.w, wd1.x, wd1.y, wd1.z, wd1.w};
        float wbs[8] = {wb0.x, wb0.y, wb0.z, wb0.w, wb1.x, wb1.y, wb1.z, wb1.w};
        #pragma unroll
        for (int i = 0; i < 4; i++)
            #pragma unroll
            for (int j = 0; j < 8; j++) {
                a[i][j] = fmaf(xs[i], wds[j], a[i][j]);
                b[i][j] = fmaf(xs[i], wbs[j], b[i][j]);
            }
    }

    #pragma unroll
    for (int i = 0; i < 4; i++) {
        int n = base + nq * 4 + i;
        if (n >= 2 * NN) continue;
        float4 a0 = make_float4(a[i][0], a[i][1], a[i][2], a[i][3]);
        float4 a1 = make_float4(a[i][4], a[i][5], a[i][6], a[i][7]);
        *(float4*)(g_A + (size_t)n * CH + co * 8)     = a0;
        *(float4*)(g_A + (size_t)n * CH + co * 8 + 4) = a1;
        __half2 h0 = __floats2half2_rn(b[i][0], b[i][1]);
        __half2 h1 = __floats2half2_rn(b[i][2], b[i][3]);
        __half2 h2 = __floats2half2_rn(b[i][4], b[i][5]);
        __half2 h3 = __floats2half2_rn(b[i][6], b[i][7]);
        uint4 bh;
        bh.x = *(unsigned*)&h0; bh.y = *(unsigned*)&h1;
        bh.z = *(unsigned*)&h2; bh.w = *(unsigned*)&h3;
        *(uint4*)(g_B + (size_t)n * 32 + co * 4) = bh;
    }
}

// ---------- mlp2: K=64. block = 64 nodes, thread = 2 nodes x 8 ch ----------
#define XS2 66    // padded row stride
__global__ void __launch_bounds__(256) k_mlp2(const float* __restrict__ W2,
                                              const float* __restrict__ b2) {
    __shared__ float sWd[CH * CH];         // 16KB
    __shared__ float sWb[CH * CH];         // 16KB
    __shared__ float sX[CH * XS2];         // ~16.5KB
    int tid = threadIdx.x;
    int base = blockIdx.x * 64;

    {
        float4* d4 = (float4*)sWd; float4* b4 = (float4*)sWb;
        const float4* gd = (const float4*)g_Wd2;
        const float4* gb = (const float4*)(W2 + CH * CH);
        #pragma unroll
        for (int i = 0; i < 4; i++) {
            d4[tid + i * 256] = gd[tid + i * 256];
            b4[tid + i * 256] = gb[tid + i * 256];
        }
    }
    #pragma unroll
    for (int i = 0; i < 4; i++) {
        int idx = tid + i * 256;             // 0..1023
        int nl = idx >> 4;                   // local node 0..63
        int j  = idx & 15;                   // float4 index within 64-float row
        int n = base + nl;
        if (n < 2 * NN) {
            float4 v = *(const float4*)(g_h + (size_t)n * CH + 4 * j);
            sX[(4 * j + 0) * XS2 + nl] = v.x;
            sX[(4 * j + 1) * XS2 + nl] = v.y;
            sX[(4 * j + 2) * XS2 + nl] = v.z;
            sX[(4 * j + 3) * XS2 + nl] = v.w;
        }
    }
    __syncthreads();

    int np = tid & 31;        // node pair
    int co = tid >> 5;        // channel oct
    float a[2][8], b[2][8];
    #pragma unroll
    for (int j = 0; j < 8; j++) {
        float bv = __ldg(b2 + co * 8 + j);
        a[0][j] = bv; a[1][j] = bv;
        b[0][j] = 0.f; b[1][j] = 0.f;
    }

    #pragma unroll
    for (int k = 0; k < CH; k++) {
        float2 xv = *(const float2*)(sX + k * XS2 + np * 2);
        float4 wd0 = *(const float4*)(sWd + k * CH + co * 8);
        float4 wd1 = *(const float4*)(sWd + k * CH + co * 8 + 4);
        float4 wb0 = *(const float4*)(sWb + k * CH + co * 8);
        float4 wb1 = *(const float4*)(sWb + k * CH + co * 8 + 4);
        float xs[2] = {xv.x, xv.y};
        float wds[8] = {wd0.x, wd0.y, wd0.z, wd0.w, wd1.x, wd1.y, wd1.z, wd1.w};
        float wbs[8] = {wb0.x, wb0.y, wb0.z, wb0.w, wb1.x, wb1.y, wb1.z, wb1.w};
        #pragma unroll
        for (int i = 0; i < 2; i++)
            #pragma unroll
            for (int j = 0; j < 8; j++) {
                a[i][j] = fmaf(xs[i], wds[j], a[i][j]);
                b[i][j] = fmaf(xs[i], wbs[j], b[i][j]);
            }
    }

    #pragma unroll
    for (int i = 0; i < 2; i++) {
        int n = base + np * 2 + i;
        if (n >= 2 * NN) continue;
        float4 a0 = make_float4(a[i][0], a[i][1], a[i][2], a[i][3]);
        float4 a1 = make_float4(a[i][4], a[i][5], a[i][6], a[i][7]);
        *(float4*)(g_A + (size_t)n * CH + co * 8)     = a0;
        *(float4*)(g_A + (size_t)n * CH + co * 8 + 4) = a1;
        __half2 h0 = __floats2half2_rn(b[i][0], b[i][1]);
        __half2 h1 = __floats2half2_rn(b[i][2], b[i][3]);
        __half2 h2 = __floats2half2_rn(b[i][4], b[i][5]);
        __half2 h3 = __floats2half2_rn(b[i][6], b[i][7]);
        uint4 bh;
        bh.x = *(unsigned*)&h0; bh.y = *(unsigned*)&h1;
        bh.z = *(unsigned*)&h2; bh.w = *(unsigned*)&h3;
        *(uint4*)(g_B + (size_t)n * 32 + co * 4) = bh;
    }
}

// ---------- edge conv: warp per node, 8 lanes x 8 ch per edge, 8 edges/iter ----------
// out[n][c] = max(0, A[n][c] + max_e B[src_e][c])   (max translation-invariant;
// relu folded into final clamp; empty node -> 0; PReLU identity on >=0)
__device__ __forceinline__ void hmax4(__half2 m[4], uint4 v) {
    m[0] = __hmax2(m[0], *(__half2*)&v.x);
    m[1] = __hmax2(m[1], *(__half2*)&v.y);
    m[2] = __hmax2(m[2], *(__half2*)&v.z);
    m[3] = __hmax2(m[3], *(__half2*)&v.w);
}

__device__ __forceinline__ void conv_node(int n, int lane, float* __restrict__ out) {
    int cnt = g_cnt[n];
    if (cnt > CAP) cnt = CAP;
    const int* sp = g_src + (size_t)n * CAP;
    int sbase = (n >= NN) ? NN : 0;
    int q = lane & 7;         // channel group: 8 halves = 16B
    int sub = lane >> 3;      // edge slot 0..3

    unsigned ninf = 0xFC00FC00u;                    // (-inf, -inf) fp16
    __half2 m[4];
    m[0] = *(__half2*)&ninf; m[1] = m[0]; m[2] = m[0]; m[3] = m[0];

    int e = 0;
    for (; e + 8 <= cnt; e += 8) {                  // 2 LDG.128 in flight per lane
        int sA = sp[e + sub] + sbase;
        int sB = sp[e + 4 + sub] + sbase;
        uint4 vA = *(const uint4*)(g_B + (size_t)sA * 32 + 4 * q);
        uint4 vB = *(const uint4*)(g_B + (size_t)sB * 32 + 4 * q);
        hmax4(m, vA);
        hmax4(m, vB);
    }
    for (; e < cnt; e += 4) {                       // predicated tail, 4 edges/iter
        int ii = e + sub;
        if (ii < cnt) {
            int s = sp[ii] + sbase;
            uint4 v = *(const uint4*)(g_B + (size_t)s * 32 + 4 * q);
            hmax4(m, v);
        }
    }
    // merge edge slots: xor 8, then xor 16
    #pragma unroll
    for (int d = 8; d <= 16; d <<= 1) {
        #pragma unroll
        for (int r = 0; r < 4; r++) {
            unsigned t = __shfl_xor_sync(0xffffffffu, *(unsigned*)&m[r], d);
            m[r] = __hmax2(m[r], *(__half2*)&t);
        }
    }

    if (sub == 0) {                                 // lanes 0..7 write 8 channels each
        float4 a0 = *(const float4*)(g_A + (size_t)n * CH + 8 * q);
        float4 a1 = *(const float4*)(g_A + (size_t)n * CH + 8 * q + 4);
        float2 f0 = __half22float2(m[0]);
        float2 f1 = __half22float2(m[1]);
        float2 f2 = __half22float2(m[2]);
        float2 f3 = __half22float2(m[3]);
        float4 r0, r1;
        r0.x = fmaxf(0.f, a0.x + f0.x); r0.y = fmaxf(0.f, a0.y + f0.y);
        r0.z = fmaxf(0.f, a0.z + f1.x); r0.w = fmaxf(0.f, a0.w + f1.y);
        r1.x = fmaxf(0.f, a1.x + f2.x); r1.y = fmaxf(0.f, a1.y + f2.y);
        r1.z = fmaxf(0.f, a1.z + f3.x); r1.w = fmaxf(0.f, a1.w + f3.y);
        *(float4*)(out + (size_t)n * CH + 8 * q)     = r0;
        *(float4*)(out + (size_t)n * CH + 8 * q + 4) = r1;
    }
}

__global__ void __launch_bounds__(256) k_conv_h() {
    int n = (blockIdx.x * blockDim.x + threadIdx.x) >> 5;
    if (n >= 2 * NN) return;
    conv_node(n, threadIdx.x & 31, g_h);
}

__global__ void __launch_bounds__(256) k_conv_out(float* __restrict__ out) {
    int n = (blockIdx.x * blockDim.x + threadIdx.x) >> 5;
    if (n >= 2 * NN) return;
    conv_node(n, threadIdx.x & 31, out);   // out laid out [e1; e2], n is global
}

extern "C" void kernel_launch(void* const* d_in, const int* in_sizes, int n_in,
                              void* d_out, int out_size) {
    const float* x1  = (const float*)d_in[0];
    const int*   ei1 = (const int*)d_in[1];    // int32 (JAX x64 disabled)
    const float* x2  = (const float*)d_in[2];
    const int*   ei2 = (const int*)d_in[3];
    const float* W1  = (const float*)d_in[4];
    const float* b1  = (const float*)d_in[5];
    // d_in[6] = prelu_a: unused — PReLU input is provably >= 0 (identity branch)
    const float* W2  = (const float*)d_in[7];
    const float* b2  = (const float*)d_in[8];
    float* out = (float*)d_out;

    const int TB = 256;
    const int gI = (2 * NN + TB - 1) / TB;
    const int gE = (2 * (NE / 8) + TB - 1) / TB;  // 8 edges per thread
    const int gM1 = (2 * NN + 127) / 128;         // 128 nodes per block
    const int gM2 = (2 * NN + 63) / 64;           // 64 nodes per block
    const int gW = (2 * NN * 32 + TB - 1) / TB;   // warp per node

    k_init<<<gI, TB>>>(W1, W2);
    k_scatter<<<gE, TB>>>(ei1, ei2);

    // layer 1
    k_mlp1<<<gM1, TB>>>(x1, x2, b1, W1);
    k_conv_h<<<gW, TB>>>();

    // layer 2
    k_mlp2<<<gM2, TB>>>(W2, b2);
    k_conv_out<<<gW, TB>>>(out);
}

// round 9
// speedup vs baseline: 1.0676x; 1.0676x over previous
#include <cuda_runtime.h>
#include <cuda_fp16.h>

#define NN 50000
#define NE 1600000
#define CH 64
#define INF 32
#define CAP 128           // per-node bucket capacity (mean deg = 32; P(>128) ~ e^-60)

// ---- device scratch (both graphs batched; no allocation allowed) ----
__device__ __align__(16)  int     g_cnt[2 * NN];
__device__ __align__(16)  int     g_src[2 * NN * CAP];
__device__ __align__(128) float   g_A[2 * NN * CH];          // per-node self term, fp32
__device__ __align__(128) __half2 g_B[2 * NN * (CH / 2)];    // gathered term, fp16 (12.8MB -> L2)
__device__ __align__(128) float   g_h[2 * NN * CH];          // layer-1 output
__device__ __align__(16)  float   g_Wd1[INF * CH];           // W1_top - W1_bot
__device__ __align__(16)  float   g_Wd2[CH * CH];            // W2_top - W2_bot

// ---------- fused init: zero counters + weight diffs ----------
__global__ void k_init(const float* __restrict__ W1, const float* __restrict__ W2) {
    int i = blockIdx.x * blockDim.x + threadIdx.x;
    if (i < 2 * NN) g_cnt[i] = 0;
    if (i < INF * CH) g_Wd1[i] = W1[i] - W1[INF * CH + i];
    if (i < CH * CH)  g_Wd2[i] = W2[i] - W2[CH * CH + i];
}

// ---------- bucket build: 8 independent edge chains per thread (MLP=8) ----------
// edge_index is int32 on device (JAX x64 disabled). Both graphs in one launch.
__global__ void k_scatter(const int* __restrict__ ei1, const int* __restrict__ ei2) {
    int t = blockIdx.x * blockDim.x + threadIdx.x;
    const int QH = NE / 8;                 // 8-edge groups per graph
    if (t >= 2 * QH) return;
    int g = t >= QH;
    int i = t - g * QH;
    const int* ei = g ? ei2 : ei1;
    int4 sa = ((const int4*)ei)[2 * i];
    int4 sb = ((const int4*)ei)[2 * i + 1];
    int4 da = ((const int4*)(ei + NE))[2 * i];
    int4 db = ((const int4*)(ei + NE))[2 * i + 1];
    int nb = g * NN;
    int n0 = nb + da.x, n1 = nb + da.y, n2 = nb + da.z, n3 = nb + da.w;
    int n4 = nb + db.x, n5 = nb + db.y, n6 = nb + db.z, n7 = nb + db.w;
    int p0 = atomicAdd(&g_cnt[n0], 1);
    int p1 = atomicAdd(&g_cnt[n1], 1);
    int p2 = atomicAdd(&g_cnt[n2], 1);
    int p3 = atomicAdd(&g_cnt[n3], 1);
    int p4 = atomicAdd(&g_cnt[n4], 1);
    int p5 = atomicAdd(&g_cnt[n5], 1);
    int p6 = atomicAdd(&g_cnt[n6], 1);
    int p7 = atomicAdd(&g_cnt[n7], 1);
    if (p0 < CAP) g_src[n0 * CAP + p0] = sa.x;
    if (p1 < CAP) g_src[n1 * CAP + p1] = sa.y;
    if (p2 < CAP) g_src[n2 * CAP + p2] = sa.z;
    if (p3 < CAP) g_src[n3 * CAP + p3] = sa.w;
    if (p4 < CAP) g_src[n4 * CAP + p4] = sb.x;
    if (p5 < CAP) g_src[n5 * CAP + p5] = sb.y;
    if (p6 < CAP) g_src[n6 * CAP + p6] = sb.z;
    if (p7 < CAP) g_src[n7 * CAP + p7] = sb.w;
}

// ---------- mlp1: register-blocked GEMM. block = 128 nodes, thread = 4 nodes x 8 ch ----------
#define XS1 132   // padded row stride for sX (breaks bank-conflict on staging stores)
__global__ void __launch_bounds__(256) k_mlp1(const float* __restrict__ x1,
                                              const float* __restrict__ x2,
                                              const float* __restrict__ b1,
                                              const float* __restrict__ W1) {
    __shared__ float sWd[INF * CH];        // 8KB
    __shared__ float sWb[INF * CH];        // 8KB
    __shared__ float sX[INF * XS1];        // ~16.5KB, k-major with pad
    int tid = threadIdx.x;
    int base = blockIdx.x * 128;

    {
        float4* d4 = (float4*)sWd; float4* b4 = (float4*)sWb;
        const float4* gd = (const float4*)g_Wd1;
        const float4* gb = (const float4*)(W1 + INF * CH);
        d4[tid] = gd[tid];           d4[tid + 256] = gd[tid + 256];
        b4[tid] = gb[tid];           b4[tid + 256] = gb[tid + 256];
    }
    #pragma unroll
    for (int i = 0; i < 4; i++) {
        int idx = tid + i * 256;             // 0..1023
        int nl = idx >> 3;                   // local node 0..127
        int j  = idx & 7;                    // float4 index within 32-float row
        int n = base + nl;
        if (n < 2 * NN) {
            const float* xr = (n < NN) ? (x1 + (size_t)n * INF)
                                       : (x2 + (size_t)(n - NN) * INF);
            float4 v = *(const float4*)(xr + 4 * j);
            sX[(4 * j + 0) * XS1 + nl] = v.x;
            sX[(4 * j + 1) * XS1 + nl] = v.y;
            sX[(4 * j + 2) * XS1 + nl] = v.z;
            sX[(4 * j + 3) * XS1 + nl] = v.w;
        }
    }
    __syncthreads();

    int nq = tid & 31;        // node quad
    int co = tid >> 5;        // channel oct (uniform per warp)
    float a[4][8], b[4][8];
    #pragma unroll
    for (int j = 0; j < 8; j++) {
        float bv = __ldg(b1 + co * 8 + j);
        #pragma unroll
        for (int i = 0; i < 4; i++) { a[i][j] = bv; b[i][j] = 0.f; }
    }

    #pragma unroll
    for (int k = 0; k < INF; k++) {
        float4 xv = *(const float4*)(sX + k * XS1 + nq * 4);
        float4 wd0 = *(const float4*)(sWd + k * CH + co * 8);
        float4 wd1 = *(const float4*)(sWd + k * CH + co * 8 + 4);
        float4 wb0 = *(const float4*)(sWb + k * CH + co * 8);
        float4 wb1 = *(const float4*)(sWb + k * CH + co * 8 + 4);
        float xs[4] = {xv.x, xv.y, xv.z, xv.w};
        float wds[8] = {wd0.x, wd0.y, wd0.z, wd0.w, wd1.x, wd1.y, wd1.z, wd1.w};
        float wbs[8] = {wb0.x, wb0.y, wb0.z, wb0.w, wb1.x, wb1.y, wb1.z, wb1.w};
        #pragma unroll
        for (int i = 0; i < 4; i++)
            #pragma unroll
            for (int j = 0; j < 8; j++) {
                a[i][j] = fmaf(xs[i], wds[j], a[i][j]);
                b[i][j] = fmaf(xs[i], wbs[j], b[i][j]);
            }
    }

    #pragma unroll
    for (int i = 0; i < 4; i++) {
        int n = base + nq * 4 + i;
        if (n >= 2 * NN) continue;
        float4 a0 = make_float4(a[i][0], a[i][1], a[i][2], a[i][3]);
        float4 a1 = make_float4(a[i][4], a[i][5], a[i][6], a[i][7]);
        *(float4*)(g_A + (size_t)n * CH + co * 8)     = a0;
        *(float4*)(g_A + (size_t)n * CH + co * 8 + 4) = a1;
        __half2 h0 = __floats2half2_rn(b[i][0], b[i][1]);
        __half2 h1 = __floats2half2_rn(b[i][2], b[i][3]);
        __half2 h2 = __floats2half2_rn(b[i][4], b[i][5]);
        __half2 h3 = __floats2half2_rn(b[i][6], b[i][7]);
        uint4 bh;
        bh.x = *(unsigned*)&h0; bh.y = *(unsigned*)&h1;
        bh.z = *(unsigned*)&h2; bh.w = *(unsigned*)&h3;
        *(uint4*)(g_B + (size_t)n * 32 + co * 4) = bh;
    }
}

// ---------- mlp2: K=64. block = 64 nodes, thread = 2 nodes x 8 ch ----------
#define XS2 66    // padded row stride
__global__ void __launch_bounds__(256) k_mlp2(const float* __restrict__ W2,
                                              const float* __restrict__ b2) {
    __shared__ float sWd[CH * CH];         // 16KB
    __shared__ float sWb[CH * CH];         // 16KB
    __shared__ float sX[CH * XS2];         // ~16.5KB
    int tid = threadIdx.x;
    int base = blockIdx.x * 64;

    {
        float4* d4 = (float4*)sWd; float4* b4 = (float4*)sWb;
        const float4* gd = (const float4*)g_Wd2;
        const float4* gb = (const float4*)(W2 + CH * CH);
        #pragma unroll
        for (int i = 0; i < 4; i++) {
            d4[tid + i * 256] = gd[tid + i * 256];
            b4[tid + i * 256] = gb[tid + i * 256];
        }
    }
    #pragma unroll
    for (int i = 0; i < 4; i++) {
        int idx = tid + i * 256;             // 0..1023
        int nl = idx >> 4;                   // local node 0..63
        int j  = idx & 15;                   // float4 index within 64-float row
        int n = base + nl;
        if (n < 2 * NN) {
            float4 v = *(const float4*)(g_h + (size_t)n * CH + 4 * j);
            sX[(4 * j + 0) * XS2 + nl] = v.x;
            sX[(4 * j + 1) * XS2 + nl] = v.y;
            sX[(4 * j + 2) * XS2 + nl] = v.z;
            sX[(4 * j + 3) * XS2 + nl] = v.w;
        }
    }
    __syncthreads();

    int np = tid & 31;        // node pair
    int co = tid >> 5;        // channel oct
    float a[2][8], b[2][8];
    #pragma unroll
    for (int j = 0; j < 8; j++) {
        float bv = __ldg(b2 + co * 8 + j);
        a[0][j] = bv; a[1][j] = bv;
        b[0][j] = 0.f; b[1][j] = 0.f;
    }

    #pragma unroll
    for (int k = 0; k < CH; k++) {
        float2 xv = *(const float2*)(sX + k * XS2 + np * 2);
        float4 wd0 = *(const float4*)(sWd + k * CH + co * 8);
        float4 wd1 = *(const float4*)(sWd + k * CH + co * 8 + 4);
        float4 wb0 = *(const float4*)(sWb + k * CH + co * 8);
        float4 wb1 = *(const float4*)(sWb + k * CH + co * 8 + 4);
        float xs[2] = {xv.x, xv.y};
        float wds[8] = {wd0.x, wd0.y, wd0.z, wd0.w, wd1.x, wd1.y, wd1.z, wd1.w};
        float wbs[8] = {wb0.x, wb0.y, wb0.z, wb0.w, wb1.x, wb1.y, wb1.z, wb1.w};
        #pragma unroll
        for (int i = 0; i < 2; i++)
            #pragma unroll
            for (int j = 0; j < 8; j++) {
                a[i][j] = fmaf(xs[i], wds[j], a[i][j]);
                b[i][j] = fmaf(xs[i], wbs[j], b[i][j]);
            }
    }

    #pragma unroll
    for (int i = 0; i < 2; i++) {
        int n = base + np * 2 + i;
        if (n >= 2 * NN) continue;
        float4 a0 = make_float4(a[i][0], a[i][1], a[i][2], a[i][3]);
        float4 a1 = make_float4(a[i][4], a[i][5], a[i][6], a[i][7]);
        *(float4*)(g_A + (size_t)n * CH + co * 8)     = a0;
        *(float4*)(g_A + (size_t)n * CH + co * 8 + 4) = a1;
        __half2 h0 = __floats2half2_rn(b[i][0], b[i][1]);
        __half2 h1 = __floats2half2_rn(b[i][2], b[i][3]);
        __half2 h2 = __floats2half2_rn(b[i][4], b[i][5]);
        __half2 h3 = __floats2half2_rn(b[i][6], b[i][7]);
        uint4 bh;
        bh.x = *(unsigned*)&h0; bh.y = *(unsigned*)&h1;
        bh.z = *(unsigned*)&h2; bh.w = *(unsigned*)&h3;
        *(uint4*)(g_B + (size_t)n * 32 + co * 4) = bh;
    }
}

// ---------- edge conv: warp per node, 8 ch-lanes x 4 edge slots, 16 edges/iter ----------
// out[n][c] = max(0, A[n][c] + max_e B[src_e][c])   (max translation-invariant;
// relu folded into final clamp; empty node -> 0; PReLU identity on >=0)
__device__ __forceinline__ void hmax4(__half2 m[4], uint4 v) {
    m[0] = __hmax2(m[0], *(__half2*)&v.x);
    m[1] = __hmax2(m[1], *(__half2*)&v.y);
    m[2] = __hmax2(m[2], *(__half2*)&v.z);
    m[3] = __hmax2(m[3], *(__half2*)&v.w);
}

__device__ __forceinline__ void conv_node(int n, int lane, float* __restrict__ out) {
    int cnt = g_cnt[n];
    if (cnt > CAP) cnt = CAP;
    const int* sp = g_src + (size_t)n * CAP;
    int sbase = (n >= NN) ? NN : 0;
    int q = lane & 7;         // channel group: 8 halves = 16B
    int sub = lane >> 3;      // edge slot 0..3

    unsigned ninf = 0xFC00FC00u;                    // (-inf, -inf) fp16
    __half2 m[4];
    m[0] = *(__half2*)&ninf; m[1] = m[0]; m[2] = m[0]; m[3] = m[0];

    int e = 0;
    // main: 16 edges/iter. One int4 index load + 4 independent LDG.128 per lane.
    for (; e + 16 <= cnt; e += 16) {
        int4 s4 = *(const int4*)(sp + e + 4 * sub);   // slot's 4 indices at once
        const __half2* p0 = g_B + (size_t)(s4.x + sbase) * 32 + 4 * q;
        const __half2* p1 = g_B + (size_t)(s4.y + sbase) * 32 + 4 * q;
        const __half2* p2 = g_B + (size_t)(s4.z + sbase) * 32 + 4 * q;
        const __half2* p3 = g_B + (size_t)(s4.w + sbase) * 32 + 4 * q;
        uint4 v0 = *(const uint4*)p0;                 // 4 loads in flight
        uint4 v1 = *(const uint4*)p1;
        uint4 v2 = *(const uint4*)p2;
        uint4 v3 = *(const uint4*)p3;
        hmax4(m, v0); hmax4(m, v1); hmax4(m, v2); hmax4(m, v3);
    }
    // tail: 4 edges/iter, predicated
    for (; e < cnt; e += 4) {
        int ii = e + sub;
        if (ii < cnt) {
            int s = sp[ii] + sbase;
            uint4 v = *(const uint4*)(g_B + (size_t)s * 32 + 4 * q);
            hmax4(m, v);
        }
    }
    // merge edge slots: xor 8, then xor 16
    #pragma unroll
    for (int d = 8; d <= 16; d <<= 1) {
        #pragma unroll
        for (int r = 0; r < 4; r++) {
            unsigned t = __shfl_xor_sync(0xffffffffu, *(unsigned*)&m[r], d);
            m[r] = __hmax2(m[r], *(__half2*)&t);
        }
    }

    if (sub == 0) {                                 // lanes 0..7 write 8 channels each
        float4 a0 = *(const float4*)(g_A + (size_t)n * CH + 8 * q);
        float4 a1 = *(const float4*)(g_A + (size_t)n * CH + 8 * q + 4);
        float2 f0 = __half22float2(m[0]);
        float2 f1 = __half22float2(m[1]);
        float2 f2 = __half22float2(m[2]);
        float2 f3 = __half22float2(m[3]);
        float4 r0, r1;
        r0.x = fmaxf(0.f, a0.x + f0.x); r0.y = fmaxf(0.f, a0.y + f0.y);
        r0.z = fmaxf(0.f, a0.z + f1.x); r0.w = fmaxf(0.f, a0.w + f1.y);
        r1.x = fmaxf(0.f, a1.x + f2.x); r1.y = fmaxf(0.f, a1.y + f2.y);
        r1.z = fmaxf(0.f, a1.z + f3.x); r1.w = fmaxf(0.f, a1.w + f3.y);
        *(float4*)(out + (size_t)n * CH + 8 * q)     = r0;
        *(float4*)(out + (size_t)n * CH + 8 * q + 4) = r1;
    }
}

__global__ void __launch_bounds__(256) k_conv_h() {
    int n = (blockIdx.x * blockDim.x + threadIdx.x) >> 5;
    if (n >= 2 * NN) return;
    conv_node(n, threadIdx.x & 31, g_h);
}

__global__ void __launch_bounds__(256) k_conv_out(float* __restrict__ out) {
    int n = (blockIdx.x * blockDim.x + threadIdx.x) >> 5;
    if (n >= 2 * NN) return;
    conv_node(n, threadIdx.x & 31, out);   // out laid out [e1; e2], n is global
}

extern "C" void kernel_launch(void* const* d_in, const int* in_sizes, int n_in,
                              void* d_out, int out_size) {
    const float* x1  = (const float*)d_in[0];
    const int*   ei1 = (const int*)d_in[1];    // int32 (JAX x64 disabled)
    const float* x2  = (const float*)d_in[2];
    const int*   ei2 = (const int*)d_in[3];
    const float* W1  = (const float*)d_in[4];
    const float* b1  = (const float*)d_in[5];
    // d_in[6] = prelu_a: unused — PReLU input is provably >= 0 (identity branch)
    const float* W2  = (const float*)d_in[7];
    const float* b2  = (const float*)d_in[8];
    float* out = (float*)d_out;

    const int TB = 256;
    const int gI = (2 * NN + TB - 1) / TB;
    const int gE = (2 * (NE / 8) + TB - 1) / TB;  // 8 edges per thread
    const int gM1 = (2 * NN + 127) / 128;         // 128 nodes per block
    const int gM2 = (2 * NN + 63) / 64;           // 64 nodes per block
    const int gW = (2 * NN * 32 + TB - 1) / TB;   // warp per node

    k_init<<<gI, TB>>>(W1, W2);
    k_scatter<<<gE, TB>>>(ei1, ei2);

    // layer 1
    k_mlp1<<<gM1, TB>>>(x1, x2, b1, W1);
    k_conv_h<<<gW, TB>>>();

    // layer 2
    k_mlp2<<<gM2, TB>>>(W2, b2);
    k_conv_out<<<gW, TB>>>(out);
}